// round 3
// baseline (speedup 1.0000x reference)
#include <cuda_runtime.h>
#include <cstdint>

// Problem constants (asserted by shapes: x [64,128,8,256], prototypes [512,256])
#define DD      256     // feature dim
#define TM      64      // tokens per CTA
#define PN      128     // protos per tile
#define KC      32      // K chunk
#define NTHREADS 256
#define PS_STRIDE 36    // padded row stride for proto tile (floats)
#define PMAX    512

// smem layout (floats):
//   xs      : TM*DD            = 16384
//   ps      : PN*PS_STRIDE     = 4608
//   pn_s    : PMAX             = 512
//   cand_d  : 64*17            = 1088
//   cand_i  : 64*17            = 1088 (ints)
//   best_d  : 64
//   best_i  : 64 (ints)
#define SMEM_FLOATS (TM*DD + PN*PS_STRIDE + PMAX + 64*17 + 64*17 + 64 + 64)
#define SMEM_BYTES  (SMEM_FLOATS * 4)

__device__ float g_pnorm[4096];

// ||p||^2 with fp64 accumulation (accuracy >> fp32 ref noise; cost negligible)
__global__ void pnorm_kernel(const float* __restrict__ protos, int P) {
    int p = blockIdx.x * blockDim.x + threadIdx.x;
    if (p >= P) return;
    const float4* row = reinterpret_cast<const float4*>(protos + (size_t)p * DD);
    double s = 0.0;
#pragma unroll
    for (int i = 0; i < DD / 4; i++) {
        float4 v = row[i];
        s += (double)v.x * v.x + (double)v.y * v.y + (double)v.z * v.z + (double)v.w * v.w;
    }
    g_pnorm[p] = (float)s;
}

__global__ __launch_bounds__(NTHREADS, 2)
void vq_kernel(const float* __restrict__ x,
               const float* __restrict__ protos,
               float* __restrict__ proto_out,
               float* __restrict__ resid_out,
               float* __restrict__ loss_out,
               int P, float loss_scale) {
    extern __shared__ float sm[];
    float* xs     = sm;                          // TM*DD
    float* ps     = xs + TM * DD;                // PN*PS_STRIDE
    float* pn_s   = ps + PN * PS_STRIDE;         // PMAX
    float* cand_d = pn_s + PMAX;                 // 64*17
    int*   cand_i = (int*)(cand_d + 64 * 17);    // 64*17
    float* best_d = (float*)(cand_i + 64 * 17);  // 64
    int*   best_i = (int*)(best_d + 64);         // 64

    const int tid = threadIdx.x;
    const int tx  = tid & 15;    // 0..15 -> proto lane
    const int ty  = tid >> 4;    // 0..15 -> token group (4 tokens each)
    const size_t tok0 = (size_t)blockIdx.x * TM;

    // ---- load X tile (64 x 256 f32 = 64KB), fully coalesced float4 ----
    {
        const float4* xg  = reinterpret_cast<const float4*>(x + tok0 * DD);
        float4*       xs4 = reinterpret_cast<float4*>(xs);
#pragma unroll
        for (int i = 0; i < (TM * DD / 4) / NTHREADS; i++)
            xs4[tid + i * NTHREADS] = xg[tid + i * NTHREADS];
    }
    // all prototype norms once
    if (tid < PMAX / 2) {
        float2 v = *reinterpret_cast<const float2*>(g_pnorm + tid * 2);
        *reinterpret_cast<float2*>(pn_s + tid * 2) = v;
    }
    if (tid < TM) { best_d[tid] = 3.4e38f; best_i[tid] = 0; }

    // proto-tile loader mapping: 256 threads cover 128 rows x 32 floats via
    // 4 (row-groups) x float4. r = tid>>3 (0..31), c4 = tid&7.
    const int lr  = tid >> 3;
    const int lc4 = tid & 7;

    const int nPT = P / PN;
    for (int pt = 0; pt < nPT; pt++) {
        const int pbase = pt * PN;

        float acc_tot[4][8];
#pragma unroll
        for (int i = 0; i < 4; i++)
#pragma unroll
            for (int j = 0; j < 8; j++) acc_tot[i][j] = 0.f;

        // prefetch chunk 0 of this tile into registers
        float4 pre[4];
#pragma unroll
        for (int rr = 0; rr < 4; rr++)
            pre[rr] = *reinterpret_cast<const float4*>(
                protos + (size_t)(pbase + lr + rr * 32) * DD + lc4 * 4);

        for (int kc = 0; kc < DD / KC; kc++) {
            __syncthreads();   // consumers done with ps from previous chunk
#pragma unroll
            for (int rr = 0; rr < 4; rr++)
                *reinterpret_cast<float4*>(ps + (lr + rr * 32) * PS_STRIDE + lc4 * 4) = pre[rr];
            // issue next chunk's global loads early (latency overlapped w/ compute)
            if (kc + 1 < DD / KC) {
#pragma unroll
                for (int rr = 0; rr < 4; rr++)
                    pre[rr] = *reinterpret_cast<const float4*>(
                        protos + (size_t)(pbase + lr + rr * 32) * DD + (kc + 1) * KC + lc4 * 4);
            } else if (pt + 1 < nPT) {
#pragma unroll
                for (int rr = 0; rr < 4; rr++)
                    pre[rr] = *reinterpret_cast<const float4*>(
                        protos + (size_t)(pbase + PN + lr + rr * 32) * DD + lc4 * 4);
            }
            __syncthreads();   // ps tile visible

            // chunk accumulators (bounds per-pair fp32 error to ~3e-5)
            float acc[4][8];
#pragma unroll
            for (int i = 0; i < 4; i++)
#pragma unroll
                for (int j = 0; j < 8; j++) acc[i][j] = 0.f;

#pragma unroll
            for (int k4 = 0; k4 < KC / 4; k4++) {
                float4 a4[4];
#pragma unroll
                for (int i = 0; i < 4; i++)
                    a4[i] = *reinterpret_cast<const float4*>(
                        xs + (ty * 4 + i) * DD + kc * KC + k4 * 4);
#pragma unroll
                for (int j = 0; j < 8; j++) {
                    float4 b = *reinterpret_cast<const float4*>(
                        ps + (j * 16 + tx) * PS_STRIDE + k4 * 4);
#pragma unroll
                    for (int i = 0; i < 4; i++) {
                        acc[i][j] = fmaf(a4[i].x, b.x, acc[i][j]);
                        acc[i][j] = fmaf(a4[i].y, b.y, acc[i][j]);
                        acc[i][j] = fmaf(a4[i].z, b.z, acc[i][j]);
                        acc[i][j] = fmaf(a4[i].w, b.w, acc[i][j]);
                    }
                }
            }
#pragma unroll
            for (int i = 0; i < 4; i++)
#pragma unroll
                for (int j = 0; j < 8; j++) acc_tot[i][j] += acc[i][j];
        }
        __syncthreads();

        // per-thread argmin over its 8 protos, per token (first-index tie-break)
#pragma unroll
        for (int i = 0; i < 4; i++) {
            float bd = 3.4e38f; int bi = 0x7fffffff;
#pragma unroll
            for (int j = 0; j < 8; j++) {
                int pidx = j * 16 + tx;
                float d = pn_s[pbase + pidx] - 2.0f * acc_tot[i][j];
                int gi = pbase + pidx;
                if (d < bd || (d == bd && gi < bi)) { bd = d; bi = gi; }
            }
            cand_d[(ty * 4 + i) * 17 + tx] = bd;
            cand_i[(ty * 4 + i) * 17 + tx] = bi;
        }
        __syncthreads();

        if (tid < TM) {
            float bd = best_d[tid]; int bi = best_i[tid];
#pragma unroll
            for (int t2 = 0; t2 < 16; t2++) {
                float d = cand_d[tid * 17 + t2];
                int  id = cand_i[tid * 17 + t2];
                if (d < bd || (d == bd && id < bi)) { bd = d; bi = id; }
            }
            best_d[tid] = bd; best_i[tid] = bi;
        }
        __syncthreads();
    }

    // ---- epilogue: gather proto row, write proto + residual, partial loss ----
    {
        int row = tid >> 2;  // 0..63
        int c0  = tid & 3;
        int bi  = best_i[row];
        const float4* pr = reinterpret_cast<const float4*>(protos + (size_t)bi * DD);
        const float4* xr = reinterpret_cast<const float4*>(xs + row * DD);
        float4* po = reinterpret_cast<float4*>(proto_out + (tok0 + row) * DD);
        float4* ro = reinterpret_cast<float4*>(resid_out + (tok0 + row) * DD);
        float ls = 0.f;
#pragma unroll
        for (int s = 0; s < 16; s++) {
            int c = c0 + s * 4;
            float4 p  = __ldg(&pr[c]);
            float4 xv = xr[c];
            float4 r;
            r.x = xv.x - p.x; r.y = xv.y - p.y;
            r.z = xv.z - p.z; r.w = xv.w - p.w;
            po[c] = p;
            ro[c] = r;
            ls += r.x * r.x + r.y * r.y + r.z * r.z + r.w * r.w;
        }
        // loss reduce: warp shuffle -> 8 partials -> lane reduce (1 barrier total)
#pragma unroll
        for (int off = 16; off > 0; off >>= 1)
            ls += __shfl_down_sync(0xffffffffu, ls, off);
        float* red = cand_d;   // reuse
        if ((tid & 31) == 0) red[tid >> 5] = ls;
        __syncthreads();
        if (tid == 0) {
            float tot = 0.f;
#pragma unroll
            for (int w = 0; w < NTHREADS / 32; w++) tot += red[w];
            atomicAdd(loss_out, tot * loss_scale);
        }
    }
}

extern "C" void kernel_launch(void* const* d_in, const int* in_sizes, int n_in,
                              void* d_out, int out_size) {
    const float* x      = (const float*)d_in[0];
    const float* protos = (const float*)d_in[1];
    const int T = in_sizes[0] / DD;   // 65536
    const int P = in_sizes[1] / DD;   // 512

    float* proto_out = (float*)d_out;
    float* resid_out = proto_out + (size_t)T * DD;
    float* loss_out  = resid_out + (size_t)T * DD;

    // zero the loss accumulator (d_out is poisoned)
    cudaMemsetAsync(loss_out, 0, sizeof(float), 0);

    pnorm_kernel<<<(P + 255) / 256, 256>>>(protos, P);

    cudaFuncSetAttribute(vq_kernel, cudaFuncAttributeMaxDynamicSharedMemorySize, SMEM_BYTES);
    float loss_scale = 1.25f / ((float)T * (float)DD);  // q + 0.25*e, both == mean(resid^2)
    vq_kernel<<<T / TM, NTHREADS, SMEM_BYTES>>>(x, protos, proto_out, resid_out,
                                                loss_out, P, loss_scale);
}